// round 6
// baseline (speedup 1.0000x reference)
#include <cuda_runtime.h>
#include <cuda_fp16.h>
#include <cstdint>
#include <cstddef>

// out = x[1024,65536] @ W2[2048,65536]^T, W2[o,l*32+c]=W_pos[o,l]*W_chan[o,c].
// fp16 operands / fp32 accum via mma.sync.m16n8k16.
// GEMM generates the B (=W2) tile on the fly from W_pos/W_chan (fp32 product,
// one rounding) -- no 256MB W2 materialization. CTA 128x128x128, 16 warps
// (warp 32x32), 3-stage cp.async for A + Wp, 3 rotating B gen buffers.

static constexpr int MB = 1024, NO = 2048, LL = 2048, CC = 32;
static constexpr int KK = LL * CC;                  // 65536

__device__ __half g_xh[(size_t)MB * KK];            // fp16 A

__device__ __forceinline__ uint32_t pk(float a, float b) {
    __half2 h = __floats2half2_rn(a, b);
    return *reinterpret_cast<uint32_t*>(&h);
}

__global__ void k_convert(const float4* __restrict__ x4) {
    int i = blockIdx.x * 256 + threadIdx.x;
    float4 v = x4[i];
    uint2 u; u.x = pk(v.x, v.y); u.y = pk(v.z, v.w);
    reinterpret_cast<uint2*>(g_xh)[i] = u;
}

__device__ __forceinline__ uint32_t smem_u32(const void* p) {
    uint32_t a;
    asm("{ .reg .u64 t; cvta.to.shared.u64 t, %1; cvt.u32.u64 %0, t; }" : "=r"(a) : "l"(p));
    return a;
}
__device__ __forceinline__ void cpa16(uint32_t s, const void* g) {
    asm volatile("cp.async.cg.shared.global [%0], [%1], 16;" :: "r"(s), "l"(g) : "memory");
}
#define CP_COMMIT() asm volatile("cp.async.commit_group;" ::: "memory")
#define CP_WAIT(n)  asm volatile("cp.async.wait_group %0;" :: "n"(n) : "memory")

__device__ __forceinline__ void ldsm4(uint32_t* r, uint32_t a) {
    asm volatile("ldmatrix.sync.aligned.m8n8.x4.shared.b16 {%0,%1,%2,%3}, [%4];"
                 : "=r"(r[0]), "=r"(r[1]), "=r"(r[2]), "=r"(r[3]) : "r"(a));
}
__device__ __forceinline__ void mma16816(float* c, const uint32_t* a,
                                         uint32_t b0, uint32_t b1) {
    asm volatile("mma.sync.aligned.m16n8k16.row.col.f32.f16.f16.f32 "
                 "{%0,%1,%2,%3}, {%4,%5,%6,%7}, {%8,%9}, {%0,%1,%2,%3};"
                 : "+f"(c[0]), "+f"(c[1]), "+f"(c[2]), "+f"(c[3])
                 : "r"(a[0]), "r"(a[1]), "r"(a[2]), "r"(a[3]), "r"(b0), "r"(b1));
}

static constexpr int BM = 128, BN = 128, KT = 128;
static constexpr int NIT = KK / KT;                 // 512
static constexpr int STG = 3;
// smem layout (bytes)
static constexpr uint32_t WC_OFF = 0;               // Wc fp32 [128][32] = 16KB
static constexpr uint32_t WP_OFF = 16384;           // Wp stages: 3 x 2KB
static constexpr uint32_t WP_STG = 2048;
static constexpr uint32_t A_OFF  = 22528;           // A stages: 3 x 32KB (256B rows)
static constexpr uint32_t A_STG  = 32768;
static constexpr uint32_t B_OFF  = 120832;          // B bufs:   3 x 32KB (256B rows)
static constexpr uint32_t B_STG  = 32768;
static constexpr uint32_t SMEM_BYTES = 219136;

// 16B-chunk swizzle for 256B rows: XOR within each 128B half
__device__ __forceinline__ uint32_t swz(uint32_t chk, uint32_t row) {
    return (chk & 8u) | ((chk & 7u) ^ (row & 7u));
}

__global__ void __launch_bounds__(512, 1) k_gemm(float* __restrict__ out,
                                                 const float* __restrict__ Wp,
                                                 const float* __restrict__ Wc) {
    extern __shared__ char smem[];
    const uint32_t sb = smem_u32(smem);
    const int t = threadIdx.x;
    const int w = t >> 5, l = t & 31;
    const int m0 = blockIdx.y * BM, n0 = blockIdx.x * BN;
    const int wm = (w >> 2) * 32, wn = (w & 3) * 32;   // 4x4 warp grid, warp 32x32

    // ---- load Wc[n0..n0+127][0..31] fp32 to smem (once) ----
    {   // 4096 floats / 512 threads = 8 floats = 2 x 16B
        const int r = t >> 2, q = t & 3;   // row 0..127, 2 quarters of 32B... use q*2 chunks
        const float* src = Wc + (size_t)(n0 + r) * CC + q * 8;
        float4 v0 = *reinterpret_cast<const float4*>(src);
        float4 v1 = *reinterpret_cast<const float4*>(src + 4);
        float4* d = reinterpret_cast<float4*>(smem + WC_OFF + r * 128 + q * 32);
        d[0] = v0; d[1] = v1;
    }

    // ---- A loader geometry: thread -> row r=t>>2 (0..127), q=t&3, chunks q+4i ----
    const int ar = t >> 2, aq = t & 3;
    const __half* gA = g_xh + (size_t)(m0 + ar) * KK;
    const uint32_t arx = (uint32_t)(ar & 7);

    auto load_stage = [&](int it, int slot) {
        // A tile: 128 rows x 128 halves (256B rows), swizzled 16B chunks
        const uint32_t ab = sb + A_OFF + (uint32_t)slot * A_STG + (uint32_t)ar * 256u;
        const __half* ga = gA + (size_t)it * KT;
#pragma unroll
        for (int i = 0; i < 4; ++i) {
            const uint32_t c = (uint32_t)(aq + 4 * i);
            cpa16(ab + (swz(c, arx) * 16u), ga + c * 8);
        }
        // Wp tile: rows n0..n0+127, cols it*4..+3 (16B per row), first 128 threads
        if (t < 128) {
            cpa16(sb + WP_OFF + (uint32_t)slot * WP_STG + (uint32_t)t * 16u,
                  Wp + (size_t)(n0 + t) * LL + (size_t)it * 4);
        }
    };

    float acc[2][4][4];
#pragma unroll
    for (int i = 0; i < 2; ++i)
#pragma unroll
        for (int j = 0; j < 4; ++j)
#pragma unroll
            for (int k = 0; k < 4; ++k) acc[i][j][k] = 0.f;

    load_stage(0, 0); CP_COMMIT();
    load_stage(1, 1); CP_COMMIT();

    // ldmatrix lane geometry (verified R3-R5)
    const int arow_i = (l & 7) + ((l >> 3) & 1) * 8, achk_i = (l >> 4);
    const int brow_i = (l & 7) + ((l >> 4) << 3),   bchk_i = (l >> 3) & 1;

    // B gen geometry: thread -> o-row go=t>>2, sub gs=t&3 (8 c's x 4 l')
    const int go = t >> 2, gs = t & 3;

    uint32_t af[2][2][4], bf[2][2][4];

    int cs = 0, ps = 2;   // consumer slot, producer slot
    for (int it = 0; it < NIT; ++it) {
        CP_WAIT(1);
        __syncthreads();   // publish A(it), Wp(it) to all threads

        // ---- generate B(it) tile into buf cs: W2[o,k]=Wp[o,l]*Wc[o,c] ----
        {
            const float4 wp4 = *reinterpret_cast<const float4*>(
                smem + WP_OFF + (uint32_t)cs * WP_STG + go * 16);
            const float4* wcp = reinterpret_cast<const float4*>(
                smem + WC_OFF + go * 128 + gs * 32);
            const float4 wc0 = wcp[0], wc1 = wcp[1];
            char* brow = smem + B_OFF + (uint32_t)cs * B_STG + go * 256;
            const float wpv[4] = {wp4.x, wp4.y, wp4.z, wp4.w};
#pragma unroll
            for (int lp = 0; lp < 4; ++lp) {
                const float wpf = wpv[lp];
                uint4 u;
                u.x = pk(wpf * wc0.x, wpf * wc0.y);
                u.y = pk(wpf * wc0.z, wpf * wc0.w);
                u.z = pk(wpf * wc1.x, wpf * wc1.y);
                u.w = pk(wpf * wc1.z, wpf * wc1.w);
                const uint32_t chk = (uint32_t)(lp * 4 + gs);
                *reinterpret_cast<uint4*>(brow + swz(chk, (uint32_t)go) * 16u) = u;
            }
        }
        __syncthreads();   // publish B(it)

        if (it + 2 < NIT) load_stage(it + 2, ps);
        CP_COMMIT();

        const uint32_t ast = sb + A_OFF + (uint32_t)cs * A_STG;
        const uint32_t bst = sb + B_OFF + (uint32_t)cs * B_STG;

        auto load_frags = [&](int ks, int buf) {
#pragma unroll
            for (int mi = 0; mi < 2; ++mi) {
                const uint32_t row = (uint32_t)(wm + mi * 16 + arow_i);
                const uint32_t chk = (uint32_t)(achk_i + ks * 2);
                ldsm4(af[buf][mi], ast + row * 256u + swz(chk, row) * 16u);
            }
#pragma unroll
            for (int nj = 0; nj < 2; ++nj) {
                const uint32_t row = (uint32_t)(wn + nj * 16 + brow_i);
                const uint32_t chk = (uint32_t)(bchk_i + ks * 2);
                ldsm4(bf[buf][nj], bst + row * 256u + swz(chk, row) * 16u);
            }
        };

        load_frags(0, 0);
#pragma unroll
        for (int ks = 0; ks < KT / 16; ++ks) {
            if (ks + 1 < KT / 16) load_frags(ks + 1, (ks + 1) & 1);
            const int bu = ks & 1;
#pragma unroll
            for (int mi = 0; mi < 2; ++mi)
#pragma unroll
                for (int j = 0; j < 4; ++j)
                    mma16816(acc[mi][j], af[bu][mi],
                             bf[bu][j >> 1][(j & 1) * 2], bf[bu][j >> 1][(j & 1) * 2 + 1]);
        }

        cs = (cs == 2) ? 0 : cs + 1;
        ps = (ps == 2) ? 0 : ps + 1;
    }

#pragma unroll
    for (int mi = 0; mi < 2; ++mi) {
        const int row = m0 + wm + mi * 16 + (l >> 2);
#pragma unroll
        for (int j = 0; j < 4; ++j) {
            const int col = n0 + wn + j * 8 + (l & 3) * 2;
            float2 lo; lo.x = acc[mi][j][0]; lo.y = acc[mi][j][1];
            float2 hi; hi.x = acc[mi][j][2]; hi.y = acc[mi][j][3];
            *reinterpret_cast<float2*>(out + (size_t)row * NO + col) = lo;
            *reinterpret_cast<float2*>(out + (size_t)(row + 8) * NO + col) = hi;
        }
    }
}

extern "C" void kernel_launch(void* const* d_in, const int* in_sizes, int n_in,
                              void* d_out, int out_size) {
    (void)in_sizes; (void)n_in; (void)out_size;
    const float* x  = (const float*)d_in[0];
    const float* Wp = (const float*)d_in[1];
    const float* Wc = (const float*)d_in[2];
    float* out = (float*)d_out;

    k_convert<<<(MB * (KK / 4)) / 256, 256>>>(reinterpret_cast<const float4*>(x));
    cudaFuncSetAttribute(k_gemm, cudaFuncAttributeMaxDynamicSharedMemorySize,
                         (int)SMEM_BYTES);
    dim3 grid(NO / BN, MB / BM);
    k_gemm<<<grid, 512, SMEM_BYTES>>>(out, Wp, Wc);
}